// round 12
// baseline (speedup 1.0000x reference)
#include <cuda_runtime.h>
#include <cuda_fp16.h>
#include <cuda_bf16.h>
#include <cstdint>

#define NMAX 100000
#define EMAX 1600000
#define HD   128

// ---------------- scratch (device globals; no allocation allowed) ----------------
__device__ __half g_h16a[NMAX * HD];    // fp16 hidden (pre-scaled by out_norm)
__device__ __half g_h16b[NMAX * HD];
__device__ __half g_m16[NMAX * HD];     // fp16 messages (GEMM output)
__device__ float g_hg[HD];
__device__ int   g_degout[NMAX];
__device__ int   g_degin[NMAX];
__device__ int   g_cursor[NMAX];
__device__ int   g_rowptr[NMAX + 1];
__device__ int   g_col[EMAX];
__device__ int   g_bsum[512];
__device__ __half g_wt1[HD * HD];       // W^T fp16: [n][k]
__device__ __half g_wt2[HD * HD];
__device__ __half g_wt3[HD * HD];
__device__ __half g_wpt[64 * HD];       // Wp fp16 [64][128], rows 40..63 zero

// ================= warp MMA helpers (baseline PTX, compiles on compute_103) ====
__device__ __forceinline__ uint32_t smem_u32(const void* p) {
    uint32_t a;
    asm("{ .reg .u64 t; cvta.to.shared.u64 t, %1; cvt.u32.u64 %0, t; }" : "=r"(a) : "l"(p));
    return a;
}
__device__ __forceinline__ void ldsm_x4(uint32_t* r, uint32_t addr) {
    asm volatile("ldmatrix.sync.aligned.m8n8.x4.shared.b16 {%0,%1,%2,%3}, [%4];"
                 : "=r"(r[0]), "=r"(r[1]), "=r"(r[2]), "=r"(r[3]) : "r"(addr));
}
__device__ __forceinline__ void mma_f16(float* d, const uint32_t* a, uint32_t b0, uint32_t b1) {
    asm volatile("mma.sync.aligned.m16n8k16.row.col.f32.f16.f16.f32 "
                 "{%0,%1,%2,%3}, {%4,%5,%6,%7}, {%8,%9}, {%0,%1,%2,%3};"
                 : "+f"(d[0]), "+f"(d[1]), "+f"(d[2]), "+f"(d[3])
                 : "r"(a[0]), "r"(a[1]), "r"(a[2]), "r"(a[3]), "r"(b0), "r"(b1));
}

#define SSTR 136   // smem row stride in halves (272B: 16B-aligned, conflict-free ldmatrix)
#define MM_SMEM (192 * SSTR * 2)    // 64-row A tile + 128-row B tile
#define CAM_SMEM (192 * SSTR * 2)   // 128-row H tile + 64-row Wp tile (fp32 Ts overlays)

// ---------------- degrees (2 edges per thread) ----------------
__global__ void k_deg(const int* __restrict__ src, const int* __restrict__ dst, int e) {
    int i = blockIdx.x * blockDim.x + threadIdx.x;
    int eh = e >> 1;
    if (i < eh) {
        int2 s = ((const int2*)src)[i];
        int2 d = ((const int2*)dst)[i];
        atomicAdd(&g_degout[s.x], 1);
        atomicAdd(&g_degout[s.y], 1);
        atomicAdd(&g_degin[d.x], 1);
        atomicAdd(&g_degin[d.y], 1);
    }
    if (i == 0 && (e & 1)) {
        atomicAdd(&g_degout[src[e - 1]], 1);
        atomicAdd(&g_degin[dst[e - 1]], 1);
    }
}

// ------- fused prep: [0,64) W^T fp16; [64,96) Wp fp16 padded; [96,..) X*out_norm fp16 -----
__global__ void k_prepall(const float* __restrict__ W1, const float* __restrict__ W2,
                          const float* __restrict__ W3, const float* __restrict__ Wp,
                          const float* __restrict__ X, __half* __restrict__ Xh, int n) {
    if (blockIdx.x < 64) {
        int t = blockIdx.x * 256 + threadIdx.x;     // < 16384
        int k = t >> 7, c = t & 127;                // t = k*128 + c
        g_wt1[c * HD + k] = __float2half(W1[t]);
        g_wt2[c * HD + k] = __float2half(W2[t]);
        g_wt3[c * HD + k] = __float2half(W3[t]);
    } else if (blockIdx.x < 96) {
        int t = (blockIdx.x - 64) * 256 + threadIdx.x;  // < 8192 = 64*128
        int r = t >> 7;
        g_wpt[t] = (r < 40) ? __float2half(Wp[t]) : __float2half(0.f);
    } else {
        int i = (blockIdx.x - 96) * 256 + threadIdx.x;  // one float4 (4 cols) per thread
        if (i < n * 32) {
            int d = g_degout[i >> 5]; if (d < 1) d = 1;
            float sv = rsqrtf((float)d);
            float4 a = ((const float4*)X)[i];
            __half2 h0 = __floats2half2_rn(a.x * sv, a.y * sv);
            __half2 h1 = __floats2half2_rn(a.z * sv, a.w * sv);
            ((__half2*)Xh)[i * 2]     = h0;
            ((__half2*)Xh)[i * 2 + 1] = h1;
        }
    }
}

// ---------------- exclusive scan of in-degrees -> row_ptr ----------------
__global__ void k_scan1(int n) {
    __shared__ int sh[512];
    int t = threadIdx.x;
    int i = blockIdx.x * 512 + t;
    int v = (i < n) ? g_degin[i] : 0;
    sh[t] = v;
    __syncthreads();
    #pragma unroll
    for (int off = 1; off < 512; off <<= 1) {
        int x = (t >= off) ? sh[t - off] : 0;
        __syncthreads();
        sh[t] += x;
        __syncthreads();
    }
    if (i < n) g_rowptr[i] = sh[t] - v;
    if (t == 511) g_bsum[blockIdx.x] = sh[511];
}

// scan2 folded in: each block serially prefixes the (<=196) block sums; also seeds cursor
__global__ void k_scan3(int nb, int n) {
    __shared__ int soff;
    if (threadIdx.x == 0) {
        int run = 0;
        for (int b = 0; b < blockIdx.x; b++) run += g_bsum[b];
        soff = run;
        if (blockIdx.x == nb - 1) g_rowptr[n] = run + g_bsum[nb - 1];
    }
    __syncthreads();
    int i = blockIdx.x * 512 + threadIdx.x;
    if (i < n) {
        int v = g_rowptr[i] + soff;
        g_rowptr[i] = v;
        g_cursor[i] = v;         // scatter cursor starts at row base
    }
}

// ---------------- CSR scatter (cursor holds absolute positions) ----------------
__global__ void k_scatter(const int* __restrict__ src, const int* __restrict__ dst, int e) {
    int i = blockIdx.x * blockDim.x + threadIdx.x;
    if (i < e) {
        int p = atomicAdd(&g_cursor[dst[i]], 1);
        g_col[p] = src[i];
    }
}

// ------------- HMMA GEMM: Y16[64-tile,128] = Xh @ W  (fp16 in/out, fp32 acc) -------------
// 64x128 block tile, warp tile 32x32: 4 ldsm : 8 mma per k-step, ~32 acc regs -> 3 CTAs/SM
__global__ void __launch_bounds__(256) k_mm(const __half* __restrict__ Xh,
                                            const __half* __restrict__ Wt,
                                            __half* __restrict__ Y, int n) {
    extern __shared__ __half sh[];
    __half* As = sh;                       // 64 x SSTR  (X rows)
    __half* Bs = sh + 64 * SSTR;           // 128 x SSTR (Wt rows: [n][k])
    int tid = threadIdx.x;
    int base = blockIdx.x * 64;

    // ---- load Xh tile (64 rows) ----
    const uint4* X4 = (const uint4*)Xh;
    #pragma unroll
    for (int i = 0; i < 4; i++) {
        int slot = i * 256 + tid;          // 1024 slots: row = slot/16, 8-half group j = slot%16
        int row = slot >> 4, j = slot & 15;
        int gr = base + row;
        uint4 v = make_uint4(0u, 0u, 0u, 0u);
        if (gr < n) v = X4[gr * 16 + j];
        *(uint4*)(As + row * SSTR + j * 8) = v;
    }
    // ---- load W^T fp16 (128 rows) ----
    const uint4* Wt4 = (const uint4*)Wt;
    #pragma unroll
    for (int i = 0; i < 8; i++) {
        int slot = i * 256 + tid;
        int row = slot >> 4, j = slot & 15;
        uint4 v = Wt4[slot];
        *(uint4*)(Bs + row * SSTR + j * 8) = v;
    }
    __syncthreads();

    int lane = tid & 31;
    int w = tid >> 5;
    int wm = (w & 1) * 32;     // row block (2 x 32)
    int wn = (w >> 1) * 32;    // col block (4 x 32)

    float acc[2][4][4];
    #pragma unroll
    for (int mi = 0; mi < 2; mi++)
        #pragma unroll
        for (int ni = 0; ni < 4; ni++)
            #pragma unroll
            for (int q = 0; q < 4; q++) acc[mi][ni][q] = 0.f;

    uint32_t a_base = smem_u32(As);
    uint32_t b_base = smem_u32(Bs);

    #pragma unroll
    for (int k0 = 0; k0 < 128; k0 += 16) {
        uint32_t af[2][4];
        #pragma unroll
        for (int mi = 0; mi < 2; mi++) {
            int row = wm + mi * 16 + (lane & 15);
            int col = k0 + (lane >> 4) * 8;
            ldsm_x4(af[mi], a_base + (uint32_t)(row * SSTR + col) * 2);
        }
        uint32_t bf[2][4];
        #pragma unroll
        for (int p = 0; p < 2; p++) {
            int row = wn + p * 16 + ((lane >> 4) & 1) * 8 + (lane & 7);
            int col = k0 + ((lane >> 3) & 1) * 8;
            ldsm_x4(bf[p], b_base + (uint32_t)(row * SSTR + col) * 2);
        }
        #pragma unroll
        for (int mi = 0; mi < 2; mi++)
            #pragma unroll
            for (int p = 0; p < 2; p++) {
                mma_f16(acc[mi][2 * p],     af[mi], bf[p][0], bf[p][1]);
                mma_f16(acc[mi][2 * p + 1], af[mi], bf[p][2], bf[p][3]);
            }
    }

    // ---- store fp16 messages ----
    __half2* Y2 = (__half2*)Y;
    #pragma unroll
    for (int mi = 0; mi < 2; mi++) {
        int r0 = base + wm + mi * 16 + (lane >> 2);
        int r1 = r0 + 8;
        #pragma unroll
        for (int ni = 0; ni < 4; ni++) {
            int col = wn + ni * 8 + (lane & 3) * 2;
            if (r0 < n) Y2[(r0 * 128 + col) >> 1] = __floats2half2_rn(acc[mi][ni][0], acc[mi][ni][1]);
            if (r1 < n) Y2[(r1 * 128 + col) >> 1] = __floats2half2_rn(acc[mi][ni][2], acc[mi][ni][3]);
        }
    }
}

// -------- aggregation core: fp16 message gather, fp32 accumulate --------
__device__ __forceinline__ float4 agg_gather(const __half* __restrict__ T, int s, int e2, int lane) {
    const uint2* T2 = (const uint2*)T;   // 4 halves per lane per row
    float4 a = make_float4(0.f, 0.f, 0.f, 0.f);
    int i = s;
    for (; i + 4 <= e2; i += 4) {
        int c0 = g_col[i], c1 = g_col[i + 1], c2 = g_col[i + 2], c3 = g_col[i + 3];
        uint2 v0 = T2[c0 * 32 + lane];
        uint2 v1 = T2[c1 * 32 + lane];
        uint2 v2 = T2[c2 * 32 + lane];
        uint2 v3 = T2[c3 * 32 + lane];
        float2 f0 = __half22float2(*(const __half2*)&v0.x);
        float2 f1 = __half22float2(*(const __half2*)&v0.y);
        float2 f2 = __half22float2(*(const __half2*)&v1.x);
        float2 f3 = __half22float2(*(const __half2*)&v1.y);
        float2 f4 = __half22float2(*(const __half2*)&v2.x);
        float2 f5 = __half22float2(*(const __half2*)&v2.y);
        float2 f6 = __half22float2(*(const __half2*)&v3.x);
        float2 f7 = __half22float2(*(const __half2*)&v3.y);
        a.x += (f0.x + f2.x) + (f4.x + f6.x);
        a.y += (f0.y + f2.y) + (f4.y + f6.y);
        a.z += (f1.x + f3.x) + (f5.x + f7.x);
        a.w += (f1.y + f3.y) + (f5.y + f7.y);
    }
    for (; i < e2; i++) {
        int c = g_col[i];
        uint2 v = T2[c * 32 + lane];
        float2 f0 = __half22float2(*(const __half2*)&v.x);
        float2 f1 = __half22float2(*(const __half2*)&v.y);
        a.x += f0.x; a.y += f0.y; a.z += f1.x; a.w += f1.y;
    }
    return a;
}

// ---- agg -> fp16 hidden pre-scaled by out_norm (layers 1,2); norms inline ----
__global__ void __launch_bounds__(256) k_agg_h(const __half* __restrict__ T,
                                               const float* __restrict__ bias,
                                               __half* __restrict__ Ho, int n) {
    int gw   = (blockIdx.x * 256 + threadIdx.x) >> 5;
    int lane = threadIdx.x & 31;
    if (gw >= n) return;
    float4 a = agg_gather(T, g_rowptr[gw], g_rowptr[gw + 1], lane);
    int dI = g_degin[gw];  if (dI < 1) dI = 1;
    int dO = g_degout[gw]; if (dO < 1) dO = 1;
    float sc = rsqrtf((float)dI);
    float on = rsqrtf((float)dO);
    float4 b = ((const float4*)bias)[lane];
    float rx = fmaxf(fmaf(a.x, sc, b.x), 0.f) * on;
    float ry = fmaxf(fmaf(a.y, sc, b.y), 0.f) * on;
    float rz = fmaxf(fmaf(a.z, sc, b.z), 0.f) * on;
    float rw = fmaxf(fmaf(a.w, sc, b.w), 0.f) * on;
    uint2 o;
    *(__half2*)&o.x = __floats2half2_rn(rx, ry);
    *(__half2*)&o.y = __floats2half2_rn(rz, rw);
    ((uint2*)Ho)[gw * 32 + lane] = o;
}

// ---- agg -> fp16 hidden, no out_norm (layer 3, feeds heads) ----
__global__ void __launch_bounds__(256) k_agg_o(const __half* __restrict__ T,
                                               const float* __restrict__ bias,
                                               __half* __restrict__ Ho, int n) {
    int gw   = (blockIdx.x * 256 + threadIdx.x) >> 5;
    int lane = threadIdx.x & 31;
    if (gw >= n) return;
    float4 a = agg_gather(T, g_rowptr[gw], g_rowptr[gw + 1], lane);
    int dI = g_degin[gw]; if (dI < 1) dI = 1;
    float sc = rsqrtf((float)dI);
    float4 b = ((const float4*)bias)[lane];
    float rx = fmaxf(fmaf(a.x, sc, b.x), 0.f);
    float ry = fmaxf(fmaf(a.y, sc, b.y), 0.f);
    float rz = fmaxf(fmaf(a.z, sc, b.z), 0.f);
    float rw = fmaxf(fmaf(a.w, sc, b.w), 0.f);
    uint2 o;
    *(__half2*)&o.x = __floats2half2_rn(rx, ry);
    *(__half2*)&o.y = __floats2half2_rn(rz, rw);
    ((uint2*)Ho)[gw * 32 + lane] = o;
}

// ---------------- seg_output ----------------
__global__ void k_seg(const float* __restrict__ Wp, const float* __restrict__ bp,
                      float* __restrict__ out, int n) {
    int c = threadIdx.x;
    if (c < 40) {
        float inv = 1.f / (float)n;
        float sum = bp[c];
        for (int k = 0; k < HD; k++) sum = fmaf(g_hg[k] * inv, Wp[c * HD + k], sum);
        out[c] = sum;
    }
}

// ---- CAM via HMMA: out[c*n + node] = dot(Wp[c,:], H[node,:]); fused column-sum of H ----
__global__ void __launch_bounds__(256) k_cam(const __half* __restrict__ Hh,
                                             float* __restrict__ out, int n) {
    extern __shared__ __half sh[];
    __half* As = sh;                    // 128 x SSTR (H tile)
    __half* Bs = sh + 128 * SSTR;       // 64 x SSTR (Wp fp16, padded)
    float*  Ts = (float*)sh;            // 128 x 65 fp32 (overlays As/Bs after mma)
    int tid = threadIdx.x;
    int base = blockIdx.x * 128;

    // ---- load H tile ----
    const uint4* H4 = (const uint4*)Hh;
    #pragma unroll
    for (int i = 0; i < 8; i++) {
        int slot = i * 256 + tid;
        int row = slot >> 4, j = slot & 15;
        int gr = base + row;
        uint4 v = make_uint4(0u, 0u, 0u, 0u);
        if (gr < n) v = H4[gr * 16 + j];
        *(uint4*)(As + row * SSTR + j * 8) = v;
    }
    // ---- load Wp fp16 (64 x 128, rows 40..63 zero) ----
    const uint4* P4 = (const uint4*)g_wpt;
    #pragma unroll
    for (int i = 0; i < 4; i++) {
        int slot = i * 256 + tid;           // 1024 slots
        int row = slot >> 4, j = slot & 15;
        uint4 v = P4[slot];
        *(uint4*)(Bs + row * SSTR + j * 8) = v;
    }
    __syncthreads();

    int lane = tid & 31;
    int w = tid >> 5;
    int wm = (w & 3) * 32;     // node rows
    int wn = (w >> 2) * 32;    // class cols

    float acc[2][4][4];
    #pragma unroll
    for (int mi = 0; mi < 2; mi++)
        #pragma unroll
        for (int ni = 0; ni < 4; ni++)
            #pragma unroll
            for (int q = 0; q < 4; q++) acc[mi][ni][q] = 0.f;

    uint32_t a_base = smem_u32(As);
    uint32_t b_base = smem_u32(Bs);

    #pragma unroll
    for (int k0 = 0; k0 < 128; k0 += 16) {
        uint32_t af[2][4];
        #pragma unroll
        for (int mi = 0; mi < 2; mi++) {
            int row = wm + mi * 16 + (lane & 15);
            int col = k0 + (lane >> 4) * 8;
            ldsm_x4(af[mi], a_base + (uint32_t)(row * SSTR + col) * 2);
        }
        uint32_t bf[2][4];
        #pragma unroll
        for (int p = 0; p < 2; p++) {
            int row = wn + p * 16 + ((lane >> 4) & 1) * 8 + (lane & 7);
            int col = k0 + ((lane >> 3) & 1) * 8;
            ldsm_x4(bf[p], b_base + (uint32_t)(row * SSTR + col) * 2);
        }
        #pragma unroll
        for (int mi = 0; mi < 2; mi++)
            #pragma unroll
            for (int p = 0; p < 2; p++) {
                mma_f16(acc[mi][2 * p],     af[mi], bf[p][0], bf[p][1]);
                mma_f16(acc[mi][2 * p + 1], af[mi], bf[p][2], bf[p][3]);
            }
    }

    // ---- fused column sum of this block's H tile (zeros beyond n are harmless) ----
    if (tid < 128) {
        float s = 0.f;
        #pragma unroll 8
        for (int r = 0; r < 128; r++) s += __half2float(As[r * SSTR + tid]);
        atomicAdd(&g_hg[tid], s);
    }
    __syncthreads();   // all reads of As/Bs done before Ts overwrite

    // ---- fragments -> padded fp32 smem tile ----
    #pragma unroll
    for (int mi = 0; mi < 2; mi++) {
        int r0 = wm + mi * 16 + (lane >> 2);
        int r1 = r0 + 8;
        #pragma unroll
        for (int ni = 0; ni < 4; ni++) {
            int col = wn + ni * 8 + (lane & 3) * 2;
            Ts[r0 * 65 + col]     = acc[mi][ni][0];
            Ts[r0 * 65 + col + 1] = acc[mi][ni][1];
            Ts[r1 * 65 + col]     = acc[mi][ni][2];
            Ts[r1 * 65 + col + 1] = acc[mi][ni][3];
        }
    }
    __syncthreads();

    // ---- coalesced transposed store: out[c*n + node] ----
    for (int idx = tid; idx < 40 * 128; idx += 256) {
        int c = idx >> 7, i = idx & 127;
        int node = base + i;
        if (node < n) out[c * n + node] = Ts[i * 65 + c];
    }
}

// ---------------- launch ----------------
extern "C" void kernel_launch(void* const* d_in, const int* in_sizes, int n_in,
                              void* d_out, int out_size) {
    const float* features = (const float*)d_in[0];
    const float* W1 = (const float*)d_in[1];
    const float* b1 = (const float*)d_in[2];
    const float* W2 = (const float*)d_in[3];
    const float* b2 = (const float*)d_in[4];
    const float* W3 = (const float*)d_in[5];
    const float* b3 = (const float*)d_in[6];
    const float* Wp = (const float*)d_in[7];
    const float* bp = (const float*)d_in[8];
    const int*  src = (const int*)d_in[9];
    const int*  dst = (const int*)d_in[10];
    float* out = (float*)d_out;

    int n = in_sizes[0] / HD;          // 100000
    int e = in_sizes[9];               // 1600000

    int ge  = (e + 255) / 256;
    int nb  = (n + 511) / 512;

    __half *h16a, *h16b, *m16, *wt1, *wt2, *wt3;
    void *degout, *degin, *hg;
    cudaGetSymbolAddress((void**)&h16a, g_h16a);
    cudaGetSymbolAddress((void**)&h16b, g_h16b);
    cudaGetSymbolAddress((void**)&m16,  g_m16);
    cudaGetSymbolAddress((void**)&wt1,  g_wt1);
    cudaGetSymbolAddress((void**)&wt2,  g_wt2);
    cudaGetSymbolAddress((void**)&wt3,  g_wt3);
    cudaGetSymbolAddress(&degout, g_degout);
    cudaGetSymbolAddress(&degin,  g_degin);
    cudaGetSymbolAddress(&hg,     g_hg);

    cudaFuncSetAttribute(k_mm,  cudaFuncAttributeMaxDynamicSharedMemorySize, MM_SMEM);
    cudaFuncSetAttribute(k_cam, cudaFuncAttributeMaxDynamicSharedMemorySize, CAM_SMEM);

    cudaMemsetAsync(degout, 0, n * sizeof(int));
    cudaMemsetAsync(degin,  0, n * sizeof(int));
    cudaMemsetAsync(hg,     0, HD * sizeof(float));

    int gt = (n + 63) / 64;     // GEMM tiles (64 rows)
    int gc = (n + 127) / 128;   // CAM tiles
    int ga = (n + 7) / 8;

    k_deg<<<(e / 2 + 255) / 256, 256>>>(src, dst, e);                               // 1
    k_prepall<<<96 + (n * 32 + 255) / 256, 256>>>(W1, W2, W3, Wp, features, h16a, n); // 2
    k_scan1<<<nb, 512>>>(n);                                                        // 3
    k_mm<<<gt, 256, MM_SMEM>>>(h16a, wt1, m16, n);                                  // 4 <- ncu profiles this
    k_scan3<<<nb, 512>>>(nb, n);                                                    // 5
    k_scatter<<<ge, 256>>>(src, dst, e);                                            // 6
    k_agg_h<<<ga, 256>>>(m16, b1, h16b, n);                                         // 7
    k_mm<<<gt, 256, MM_SMEM>>>(h16b, wt2, m16, n);                                  // 8
    k_agg_h<<<ga, 256>>>(m16, b2, h16a, n);                                         // 9
    k_mm<<<gt, 256, MM_SMEM>>>(h16a, wt3, m16, n);                                  // 10
    k_agg_o<<<ga, 256>>>(m16, b3, h16b, n);                                         // 11

    // heads (fp16 H in h16b): cam fuses colsum; seg reads g_hg after cam
    k_cam<<<gc, 256, CAM_SMEM>>>(h16b, out + 40, n);                                // 12
    k_seg<<<1, 64>>>(Wp, bp, out, n);                                               // 13
}

// round 13
// speedup vs baseline: 1.0339x; 1.0339x over previous
#include <cuda_runtime.h>
#include <cuda_fp16.h>
#include <cuda_bf16.h>
#include <cstdint>

#define NMAX 100000
#define EMAX 1600000
#define HD   128

// ---------------- scratch (device globals; no allocation allowed) ----------------
__device__ __half g_h16a[NMAX * HD];    // fp16 hidden (pre-scaled by out_norm)
__device__ __half g_h16b[NMAX * HD];
__device__ __half g_m16[NMAX * HD];     // fp16 messages (GEMM output)
__device__ float g_hg[HD];
__device__ int   g_degout[NMAX];
__device__ int   g_degin[NMAX];
__device__ int   g_cursor[NMAX];
__device__ int   g_rowptr[NMAX + 1];
__device__ int   g_col[EMAX];
__device__ int   g_bsum[512];
__device__ __half g_wt1[HD * HD];       // W^T fp16: [n][k]
__device__ __half g_wt2[HD * HD];
__device__ __half g_wt3[HD * HD];
__device__ __half g_wpt[64 * HD];       // Wp fp16 [64][128], rows 40..63 zero

// ================= warp MMA helpers (baseline PTX, compiles on compute_103) ====
__device__ __forceinline__ uint32_t smem_u32(const void* p) {
    uint32_t a;
    asm("{ .reg .u64 t; cvta.to.shared.u64 t, %1; cvt.u32.u64 %0, t; }" : "=r"(a) : "l"(p));
    return a;
}
__device__ __forceinline__ void ldsm_x4(uint32_t* r, uint32_t addr) {
    asm volatile("ldmatrix.sync.aligned.m8n8.x4.shared.b16 {%0,%1,%2,%3}, [%4];"
                 : "=r"(r[0]), "=r"(r[1]), "=r"(r[2]), "=r"(r[3]) : "r"(addr));
}
__device__ __forceinline__ void mma_f16(float* d, const uint32_t* a, uint32_t b0, uint32_t b1) {
    asm volatile("mma.sync.aligned.m16n8k16.row.col.f32.f16.f16.f32 "
                 "{%0,%1,%2,%3}, {%4,%5,%6,%7}, {%8,%9}, {%0,%1,%2,%3};"
                 : "+f"(d[0]), "+f"(d[1]), "+f"(d[2]), "+f"(d[3])
                 : "r"(a[0]), "r"(a[1]), "r"(a[2]), "r"(a[3]), "r"(b0), "r"(b1));
}
__device__ __forceinline__ void cp_async16(uint32_t daddr, const void* gptr, int nbytes) {
    asm volatile("cp.async.cg.shared.global [%0], [%1], 16, %2;"
                 :: "r"(daddr), "l"(gptr), "r"(nbytes) : "memory");
}
__device__ __forceinline__ void cp_commit() { asm volatile("cp.async.commit_group;" ::: "memory"); }

#define SSTR 136   // smem row stride in halves for cam (272B)
#define CSTR 72    // k_mm chunk row stride in halves (144B: 16B-aligned, 16B bank shift)
#define MM_SMEM (4 * 128 * CSTR * 2)    // A0,B0,A1,B1 = 73728 B
#define CAM_SMEM (192 * SSTR * 2)       // 128-row H tile + 64-row Wp tile (fp32 Ts overlays)

// ---------------- degrees (2 edges per thread) ----------------
__global__ void k_deg(const int* __restrict__ src, const int* __restrict__ dst, int e) {
    int i = blockIdx.x * blockDim.x + threadIdx.x;
    int eh = e >> 1;
    if (i < eh) {
        int2 s = ((const int2*)src)[i];
        int2 d = ((const int2*)dst)[i];
        atomicAdd(&g_degout[s.x], 1);
        atomicAdd(&g_degout[s.y], 1);
        atomicAdd(&g_degin[d.x], 1);
        atomicAdd(&g_degin[d.y], 1);
    }
    if (i == 0 && (e & 1)) {
        atomicAdd(&g_degout[src[e - 1]], 1);
        atomicAdd(&g_degin[dst[e - 1]], 1);
    }
}

// ------- fused prep: [0,64) W^T fp16; [64,96) Wp fp16 padded; [96,..) X*out_norm fp16 -----
__global__ void k_prepall(const float* __restrict__ W1, const float* __restrict__ W2,
                          const float* __restrict__ W3, const float* __restrict__ Wp,
                          const float* __restrict__ X, __half* __restrict__ Xh, int n) {
    if (blockIdx.x < 64) {
        int t = blockIdx.x * 256 + threadIdx.x;     // < 16384
        int k = t >> 7, c = t & 127;                // t = k*128 + c
        g_wt1[c * HD + k] = __float2half(W1[t]);
        g_wt2[c * HD + k] = __float2half(W2[t]);
        g_wt3[c * HD + k] = __float2half(W3[t]);
    } else if (blockIdx.x < 96) {
        int t = (blockIdx.x - 64) * 256 + threadIdx.x;  // < 8192 = 64*128
        int r = t >> 7;
        g_wpt[t] = (r < 40) ? __float2half(Wp[t]) : __float2half(0.f);
    } else {
        int i = (blockIdx.x - 96) * 256 + threadIdx.x;  // one float4 (4 cols) per thread
        if (i < n * 32) {
            int d = g_degout[i >> 5]; if (d < 1) d = 1;
            float sv = rsqrtf((float)d);
            float4 a = ((const float4*)X)[i];
            __half2 h0 = __floats2half2_rn(a.x * sv, a.y * sv);
            __half2 h1 = __floats2half2_rn(a.z * sv, a.w * sv);
            ((__half2*)Xh)[i * 2]     = h0;
            ((__half2*)Xh)[i * 2 + 1] = h1;
        }
    }
}

// ---------------- exclusive scan of in-degrees -> row_ptr ----------------
__global__ void k_scan1(int n) {
    __shared__ int sh[512];
    int t = threadIdx.x;
    int i = blockIdx.x * 512 + t;
    int v = (i < n) ? g_degin[i] : 0;
    sh[t] = v;
    __syncthreads();
    #pragma unroll
    for (int off = 1; off < 512; off <<= 1) {
        int x = (t >= off) ? sh[t - off] : 0;
        __syncthreads();
        sh[t] += x;
        __syncthreads();
    }
    if (i < n) g_rowptr[i] = sh[t] - v;
    if (t == 511) g_bsum[blockIdx.x] = sh[511];
}

// scan2 folded in: each block serially prefixes the (<=196) block sums; also seeds cursor
__global__ void k_scan3(int nb, int n) {
    __shared__ int soff;
    if (threadIdx.x == 0) {
        int run = 0;
        for (int b = 0; b < blockIdx.x; b++) run += g_bsum[b];
        soff = run;
        if (blockIdx.x == nb - 1) g_rowptr[n] = run + g_bsum[nb - 1];
    }
    __syncthreads();
    int i = blockIdx.x * 512 + threadIdx.x;
    if (i < n) {
        int v = g_rowptr[i] + soff;
        g_rowptr[i] = v;
        g_cursor[i] = v;         // scatter cursor starts at row base
    }
}

// ---------------- CSR scatter (cursor holds absolute positions) ----------------
__global__ void k_scatter(const int* __restrict__ src, const int* __restrict__ dst, int e) {
    int i = blockIdx.x * blockDim.x + threadIdx.x;
    if (i < e) {
        int p = atomicAdd(&g_cursor[dst[i]], 1);
        g_col[p] = src[i];
    }
}

// ------------- HMMA GEMM: Y16[128-tile,128] = Xh @ W, split-K cp.async pipeline ----------
// 128x128 block tile, warp 32x64 (6 ldsm : 16 mma); K in two 64-chunks, double-buffered.
__global__ void __launch_bounds__(256) k_mm(const __half* __restrict__ Xh,
                                            const __half* __restrict__ Wt,
                                            __half* __restrict__ Y, int n) {
    extern __shared__ __half sh[];
    __half* Abuf[2] = { sh,                sh + 2 * 128 * CSTR };
    __half* Bbuf[2] = { sh + 128 * CSTR,   sh + 3 * 128 * CSTR };
    int tid = threadIdx.x;
    int base = blockIdx.x * 128;

    // ---- issue both chunk loads via cp.async ----
    #pragma unroll
    for (int ch = 0; ch < 2; ch++) {
        uint32_t asb = smem_u32(Abuf[ch]);
        uint32_t bsb = smem_u32(Bbuf[ch]);
        #pragma unroll
        for (int i = 0; i < 4; i++) {
            int slot = i * 256 + tid;          // 1024: row = slot/8, 8-half group j = slot%8
            int row = slot >> 3, j = slot & 7;
            int gr = base + row;
            const __half* gp = Xh + ((size_t)(gr < n ? gr : 0) * 128 + ch * 64 + j * 8);
            cp_async16(asb + (uint32_t)(row * CSTR + j * 8) * 2, gp, (gr < n) ? 16 : 0);
        }
        #pragma unroll
        for (int i = 0; i < 4; i++) {
            int slot = i * 256 + tid;
            int row = slot >> 3, j = slot & 7;
            const __half* gp = Wt + (row * 128 + ch * 64 + j * 8);
            cp_async16(bsb + (uint32_t)(row * CSTR + j * 8) * 2, gp, 16);
        }
        cp_commit();
    }

    int lane = tid & 31;
    int w = tid >> 5;
    int wm = (w & 3) * 32;     // row block
    int wn = (w >> 2) * 64;    // col block

    float acc[2][8][4];
    #pragma unroll
    for (int mi = 0; mi < 2; mi++)
        #pragma unroll
        for (int ni = 0; ni < 8; ni++)
            #pragma unroll
            for (int q = 0; q < 4; q++) acc[mi][ni][q] = 0.f;

    #pragma unroll
    for (int ch = 0; ch < 2; ch++) {
        if (ch == 0) asm volatile("cp.async.wait_group 1;" ::: "memory");
        else         asm volatile("cp.async.wait_group 0;" ::: "memory");
        __syncthreads();
        uint32_t a_base = smem_u32(Abuf[ch]);
        uint32_t b_base = smem_u32(Bbuf[ch]);
        #pragma unroll
        for (int k0 = 0; k0 < 64; k0 += 16) {
            uint32_t af[2][4];
            #pragma unroll
            for (int mi = 0; mi < 2; mi++) {
                int row = wm + mi * 16 + (lane & 15);
                int col = k0 + (lane >> 4) * 8;
                ldsm_x4(af[mi], a_base + (uint32_t)(row * CSTR + col) * 2);
            }
            uint32_t bf[4][4];
            #pragma unroll
            for (int p = 0; p < 4; p++) {
                int row = wn + p * 16 + ((lane >> 4) & 1) * 8 + (lane & 7);
                int col = k0 + ((lane >> 3) & 1) * 8;
                ldsm_x4(bf[p], b_base + (uint32_t)(row * CSTR + col) * 2);
            }
            #pragma unroll
            for (int mi = 0; mi < 2; mi++)
                #pragma unroll
                for (int p = 0; p < 4; p++) {
                    mma_f16(acc[mi][2 * p],     af[mi], bf[p][0], bf[p][1]);
                    mma_f16(acc[mi][2 * p + 1], af[mi], bf[p][2], bf[p][3]);
                }
        }
    }

    // ---- store fp16 messages ----
    __half2* Y2 = (__half2*)Y;
    #pragma unroll
    for (int mi = 0; mi < 2; mi++) {
        int r0 = base + wm + mi * 16 + (lane >> 2);
        int r1 = r0 + 8;
        #pragma unroll
        for (int ni = 0; ni < 8; ni++) {
            int col = wn + ni * 8 + (lane & 3) * 2;
            if (r0 < n) Y2[(r0 * 128 + col) >> 1] = __floats2half2_rn(acc[mi][ni][0], acc[mi][ni][1]);
            if (r1 < n) Y2[(r1 * 128 + col) >> 1] = __floats2half2_rn(acc[mi][ni][2], acc[mi][ni][3]);
        }
    }
}

// -------- aggregation core: fp16 message gather, fp32 accumulate --------
__device__ __forceinline__ float4 agg_gather(const __half* __restrict__ T, int s, int e2, int lane) {
    const uint2* T2 = (const uint2*)T;   // 4 halves per lane per row
    float4 a = make_float4(0.f, 0.f, 0.f, 0.f);
    int i = s;
    for (; i + 4 <= e2; i += 4) {
        int c0 = g_col[i], c1 = g_col[i + 1], c2 = g_col[i + 2], c3 = g_col[i + 3];
        uint2 v0 = T2[c0 * 32 + lane];
        uint2 v1 = T2[c1 * 32 + lane];
        uint2 v2 = T2[c2 * 32 + lane];
        uint2 v3 = T2[c3 * 32 + lane];
        float2 f0 = __half22float2(*(const __half2*)&v0.x);
        float2 f1 = __half22float2(*(const __half2*)&v0.y);
        float2 f2 = __half22float2(*(const __half2*)&v1.x);
        float2 f3 = __half22float2(*(const __half2*)&v1.y);
        float2 f4 = __half22float2(*(const __half2*)&v2.x);
        float2 f5 = __half22float2(*(const __half2*)&v2.y);
        float2 f6 = __half22float2(*(const __half2*)&v3.x);
        float2 f7 = __half22float2(*(const __half2*)&v3.y);
        a.x += (f0.x + f2.x) + (f4.x + f6.x);
        a.y += (f0.y + f2.y) + (f4.y + f6.y);
        a.z += (f1.x + f3.x) + (f5.x + f7.x);
        a.w += (f1.y + f3.y) + (f5.y + f7.y);
    }
    for (; i < e2; i++) {
        int c = g_col[i];
        uint2 v = T2[c * 32 + lane];
        float2 f0 = __half22float2(*(const __half2*)&v.x);
        float2 f1 = __half22float2(*(const __half2*)&v.y);
        a.x += f0.x; a.y += f0.y; a.z += f1.x; a.w += f1.y;
    }
    return a;
}

// ---- agg -> fp16 hidden pre-scaled by out_norm (layers 1,2); norms inline ----
__global__ void __launch_bounds__(256) k_agg_h(const __half* __restrict__ T,
                                               const float* __restrict__ bias,
                                               __half* __restrict__ Ho, int n) {
    int gw   = (blockIdx.x * 256 + threadIdx.x) >> 5;
    int lane = threadIdx.x & 31;
    if (gw >= n) return;
    float4 a = agg_gather(T, g_rowptr[gw], g_rowptr[gw + 1], lane);
    int dI = g_degin[gw];  if (dI < 1) dI = 1;
    int dO = g_degout[gw]; if (dO < 1) dO = 1;
    float sc = rsqrtf((float)dI);
    float on = rsqrtf((float)dO);
    float4 b = ((const float4*)bias)[lane];
    float rx = fmaxf(fmaf(a.x, sc, b.x), 0.f) * on;
    float ry = fmaxf(fmaf(a.y, sc, b.y), 0.f) * on;
    float rz = fmaxf(fmaf(a.z, sc, b.z), 0.f) * on;
    float rw = fmaxf(fmaf(a.w, sc, b.w), 0.f) * on;
    uint2 o;
    *(__half2*)&o.x = __floats2half2_rn(rx, ry);
    *(__half2*)&o.y = __floats2half2_rn(rz, rw);
    ((uint2*)Ho)[gw * 32 + lane] = o;
}

// ---- agg -> fp16 hidden, no out_norm (layer 3, feeds heads) ----
__global__ void __launch_bounds__(256) k_agg_o(const __half* __restrict__ T,
                                               const float* __restrict__ bias,
                                               __half* __restrict__ Ho, int n) {
    int gw   = (blockIdx.x * 256 + threadIdx.x) >> 5;
    int lane = threadIdx.x & 31;
    if (gw >= n) return;
    float4 a = agg_gather(T, g_rowptr[gw], g_rowptr[gw + 1], lane);
    int dI = g_degin[gw]; if (dI < 1) dI = 1;
    float sc = rsqrtf((float)dI);
    float4 b = ((const float4*)bias)[lane];
    float rx = fmaxf(fmaf(a.x, sc, b.x), 0.f);
    float ry = fmaxf(fmaf(a.y, sc, b.y), 0.f);
    float rz = fmaxf(fmaf(a.z, sc, b.z), 0.f);
    float rw = fmaxf(fmaf(a.w, sc, b.w), 0.f);
    uint2 o;
    *(__half2*)&o.x = __floats2half2_rn(rx, ry);
    *(__half2*)&o.y = __floats2half2_rn(rz, rw);
    ((uint2*)Ho)[gw * 32 + lane] = o;
}

// ---------------- seg_output ----------------
__global__ void k_seg(const float* __restrict__ Wp, const float* __restrict__ bp,
                      float* __restrict__ out, int n) {
    int c = threadIdx.x;
    if (c < 40) {
        float inv = 1.f / (float)n;
        float sum = bp[c];
        for (int k = 0; k < HD; k++) sum = fmaf(g_hg[k] * inv, Wp[c * HD + k], sum);
        out[c] = sum;
    }
}

// ---- CAM via HMMA: out[c*n + node] = dot(Wp[c,:], H[node,:]); fused column-sum of H ----
__global__ void __launch_bounds__(256) k_cam(const __half* __restrict__ Hh,
                                             float* __restrict__ out, int n) {
    extern __shared__ __half sh[];
    __half* As = sh;                    // 128 x SSTR (H tile)
    __half* Bs = sh + 128 * SSTR;       // 64 x SSTR (Wp fp16, padded)
    float*  Ts = (float*)sh;            // 128 x 65 fp32 (overlays As/Bs after mma)
    int tid = threadIdx.x;
    int base = blockIdx.x * 128;

    // ---- load H tile ----
    const uint4* H4 = (const uint4*)Hh;
    #pragma unroll
    for (int i = 0; i < 8; i++) {
        int slot = i * 256 + tid;
        int row = slot >> 4, j = slot & 15;
        int gr = base + row;
        uint4 v = make_uint4(0u, 0u, 0u, 0u);
        if (gr < n) v = H4[gr * 16 + j];
        *(uint4*)(As + row * SSTR + j * 8) = v;
    }
    // ---- load Wp fp16 (64 x 128, rows 40..63 zero) ----
    const uint4* P4 = (const uint4*)g_wpt;
    #pragma unroll
    for (int i = 0; i < 4; i++) {
        int slot = i * 256 + tid;           // 1024 slots
        int row = slot >> 4, j = slot & 15;
        uint4 v = P4[slot];
        *(uint4*)(Bs + row * SSTR + j * 8) = v;
    }
    __syncthreads();

    int lane = tid & 31;
    int w = tid >> 5;
    int wm = (w & 3) * 32;     // node rows
    int wn = (w >> 2) * 32;    // class cols

    float acc[2][4][4];
    #pragma unroll
    for (int mi = 0; mi < 2; mi++)
        #pragma unroll
        for (int ni = 0; ni < 4; ni++)
            #pragma unroll
            for (int q = 0; q < 4; q++) acc[mi][ni][q] = 0.f;

    uint32_t a_base = smem_u32(As);
    uint32_t b_base = smem_u32(Bs);

    #pragma unroll
    for (int k0 = 0; k0 < 128; k0 += 16) {
        uint32_t af[2][4];
        #pragma unroll
        for (int mi = 0; mi < 2; mi++) {
            int row = wm + mi * 16 + (lane & 15);
            int col = k0 + (lane >> 4) * 8;
            ldsm_x4(af[mi], a_base + (uint32_t)(row * SSTR + col) * 2);
        }
        uint32_t bf[2][4];
        #pragma unroll
        for (int p = 0; p < 2; p++) {
            int row = wn + p * 16 + ((lane >> 4) & 1) * 8 + (lane & 7);
            int col = k0 + ((lane >> 3) & 1) * 8;
            ldsm_x4(bf[p], b_base + (uint32_t)(row * SSTR + col) * 2);
        }
        #pragma unroll
        for (int mi = 0; mi < 2; mi++)
            #pragma unroll
            for (int p = 0; p < 2; p++) {
                mma_f16(acc[mi][2 * p],     af[mi], bf[p][0], bf[p][1]);
                mma_f16(acc[mi][2 * p + 1], af[mi], bf[p][2], bf[p][3]);
            }
    }

    // ---- fused column sum of this block's H tile (zeros beyond n are harmless) ----
    if (tid < 128) {
        float s = 0.f;
        #pragma unroll 8
        for (int r = 0; r < 128; r++) s += __half2float(As[r * SSTR + tid]);
        atomicAdd(&g_hg[tid], s);
    }
    __syncthreads();   // all reads of As/Bs done before Ts overwrite

    // ---- fragments -> padded fp32 smem tile ----
    #pragma unroll
    for (int mi = 0; mi < 2; mi++) {
        int r0 = wm + mi * 16 + (lane >> 2);
        int r1 = r0 + 8;
        #pragma unroll
        for (int ni = 0; ni < 4; ni++) {
            int col = wn + ni * 8 + (lane & 3) * 2;
            Ts[r0 * 65 + col]     = acc[mi][ni][0];
            Ts[r0 * 65 + col + 1] = acc[mi][ni][1];
            Ts[r1 * 65 + col]     = acc[mi][ni][2];
            Ts[r1 * 65 + col + 1] = acc[mi][ni][3];
        }
    }
    __syncthreads();

    // ---- coalesced transposed store: out[c*n + node] ----
    for (int idx = tid; idx < 40 * 128; idx += 256) {
        int c = idx >> 7, i = idx & 127;
        int node = base + i;
        if (node < n) out[c * n + node] = Ts[i * 65 + c];
    }
}

// ---------------- launch ----------------
extern "C" void kernel_launch(void* const* d_in, const int* in_sizes, int n_in,
                              void* d_out, int out_size) {
    const float* features = (const float*)d_in[0];
    const float* W1 = (const float*)d_in[1];
    const float* b1 = (const float*)d_in[2];
    const float* W2 = (const float*)d_in[3];
    const float* b2 = (const float*)d_in[4];
    const float* W3 = (const float*)d_in[5];
    const float* b3 = (const float*)d_in[6];
    const float* Wp = (const float*)d_in[7];
    const float* bp = (const float*)d_in[8];
    const int*  src = (const int*)d_in[9];
    const int*  dst = (const int*)d_in[10];
    float* out = (float*)d_out;

    int n = in_sizes[0] / HD;          // 100000
    int e = in_sizes[9];               // 1600000

    int ge  = (e + 255) / 256;
    int nb  = (n + 511) / 512;

    __half *h16a, *h16b, *m16, *wt1, *wt2, *wt3;
    void *degout, *degin, *hg;
    cudaGetSymbolAddress((void**)&h16a, g_h16a);
    cudaGetSymbolAddress((void**)&h16b, g_h16b);
    cudaGetSymbolAddress((void**)&m16,  g_m16);
    cudaGetSymbolAddress((void**)&wt1,  g_wt1);
    cudaGetSymbolAddress((void**)&wt2,  g_wt2);
    cudaGetSymbolAddress((void**)&wt3,  g_wt3);
    cudaGetSymbolAddress(&degout, g_degout);
    cudaGetSymbolAddress(&degin,  g_degin);
    cudaGetSymbolAddress(&hg,     g_hg);

    cudaFuncSetAttribute(k_mm,  cudaFuncAttributeMaxDynamicSharedMemorySize, MM_SMEM);
    cudaFuncSetAttribute(k_cam, cudaFuncAttributeMaxDynamicSharedMemorySize, CAM_SMEM);

    cudaMemsetAsync(degout, 0, n * sizeof(int));
    cudaMemsetAsync(degin,  0, n * sizeof(int));
    cudaMemsetAsync(hg,     0, HD * sizeof(float));

    int gt = (n + 127) / 128;   // GEMM tiles (128 rows)
    int gc = (n + 127) / 128;   // CAM tiles
    int ga = (n + 7) / 8;

    k_deg<<<(e / 2 + 255) / 256, 256>>>(src, dst, e);                               // 1
    k_prepall<<<96 + (n * 32 + 255) / 256, 256>>>(W1, W2, W3, Wp, features, h16a, n); // 2
    k_scan1<<<nb, 512>>>(n);                                                        // 3
    k_mm<<<gt, 256, MM_SMEM>>>(h16a, wt1, m16, n);                                  // 4 <- ncu profiles this
    k_scan3<<<nb, 512>>>(nb, n);                                                    // 5
    k_scatter<<<ge, 256>>>(src, dst, e);                                            // 6
    k_agg_h<<<ga, 256>>>(m16, b1, h16b, n);                                         // 7
    k_mm<<<gt, 256, MM_SMEM>>>(h16b, wt2, m16, n);                                  // 8
    k_agg_h<<<ga, 256>>>(m16, b2, h16a, n);                                         // 9
    k_mm<<<gt, 256, MM_SMEM>>>(h16a, wt3, m16, n);                                  // 10
    k_agg_o<<<ga, 256>>>(m16, b3, h16b, n);                                         // 11

    // heads (fp16 H in h16b): cam fuses colsum; seg reads g_hg after cam
    k_cam<<<gc, 256, CAM_SMEM>>>(h16b, out + 40, n);                                // 12
    k_seg<<<1, 64>>>(Wp, bp, out, n);                                               // 13
}

// round 14
// speedup vs baseline: 1.0638x; 1.0289x over previous
#include <cuda_runtime.h>
#include <cuda_fp16.h>
#include <cuda_bf16.h>
#include <cstdint>

#define NMAX 100000
#define EMAX 1600000
#define HD   128

// ---------------- scratch (device globals; no allocation allowed) ----------------
__device__ __half g_h16a[NMAX * HD];    // fp16 hidden (pre-scaled by out_norm)
__device__ __half g_h16b[NMAX * HD];
__device__ __half g_m16[NMAX * HD];     // fp16 messages (GEMM output)
__device__ float g_hg[HD];
__device__ int   g_degout[NMAX];
__device__ int   g_degin[NMAX];
__device__ int   g_cursor[NMAX];
__device__ int   g_rowptr[NMAX + 1];
__device__ int   g_col[EMAX];
__device__ int   g_bsum[512];
__device__ __half g_wt1[HD * HD];       // W^T fp16: [n][k]
__device__ __half g_wt2[HD * HD];
__device__ __half g_wt3[HD * HD];
__device__ __half g_wpt[64 * HD];       // Wp fp16 [64][128], rows 40..63 zero

// ================= warp MMA helpers (baseline PTX, compiles on compute_103) ====
__device__ __forceinline__ uint32_t smem_u32(const void* p) {
    uint32_t a;
    asm("{ .reg .u64 t; cvta.to.shared.u64 t, %1; cvt.u32.u64 %0, t; }" : "=r"(a) : "l"(p));
    return a;
}
__device__ __forceinline__ void ldsm_x4(uint32_t* r, uint32_t addr) {
    asm volatile("ldmatrix.sync.aligned.m8n8.x4.shared.b16 {%0,%1,%2,%3}, [%4];"
                 : "=r"(r[0]), "=r"(r[1]), "=r"(r[2]), "=r"(r[3]) : "r"(addr));
}
__device__ __forceinline__ void mma_f16(float* d, const uint32_t* a, uint32_t b0, uint32_t b1) {
    asm volatile("mma.sync.aligned.m16n8k16.row.col.f32.f16.f16.f32 "
                 "{%0,%1,%2,%3}, {%4,%5,%6,%7}, {%8,%9}, {%0,%1,%2,%3};"
                 : "+f"(d[0]), "+f"(d[1]), "+f"(d[2]), "+f"(d[3])
                 : "r"(a[0]), "r"(a[1]), "r"(a[2]), "r"(a[3]), "r"(b0), "r"(b1));
}
__device__ __forceinline__ void cp_async16(uint32_t daddr, const void* gptr, int nbytes) {
    asm volatile("cp.async.cg.shared.global [%0], [%1], 16, %2;"
                 :: "r"(daddr), "l"(gptr), "r"(nbytes) : "memory");
}
__device__ __forceinline__ void cp_commit() { asm volatile("cp.async.commit_group;" ::: "memory"); }

#define SSTR 136   // smem row stride in halves for cam (272B)
#define CSTR 72    // k_mm chunk row stride in halves (144B: 16B-aligned, 16B bank shift)
#define MM_SMEM (4 * 128 * CSTR * 2)    // A0,B0,A1,B1 = 73728 B
#define CAM_SMEM (192 * SSTR * 2)       // 128-row H tile + 64-row Wp tile (fp32 Ts overlays)

// ---------------- degrees (2 edges per thread) ----------------
__global__ void k_deg(const int* __restrict__ src, const int* __restrict__ dst, int e) {
    int i = blockIdx.x * blockDim.x + threadIdx.x;
    int eh = e >> 1;
    if (i < eh) {
        int2 s = ((const int2*)src)[i];
        int2 d = ((const int2*)dst)[i];
        atomicAdd(&g_degout[s.x], 1);
        atomicAdd(&g_degout[s.y], 1);
        atomicAdd(&g_degin[d.x], 1);
        atomicAdd(&g_degin[d.y], 1);
    }
    if (i == 0 && (e & 1)) {
        atomicAdd(&g_degout[src[e - 1]], 1);
        atomicAdd(&g_degin[dst[e - 1]], 1);
    }
}

// ------- fused prep: [0,64) W^T fp16; [64,96) Wp fp16 padded; [96,..) X*out_norm fp16 -----
__global__ void k_prepall(const float* __restrict__ W1, const float* __restrict__ W2,
                          const float* __restrict__ W3, const float* __restrict__ Wp,
                          const float* __restrict__ X, __half* __restrict__ Xh, int n) {
    if (blockIdx.x < 64) {
        int t = blockIdx.x * 256 + threadIdx.x;     // < 16384
        int k = t >> 7, c = t & 127;                // t = k*128 + c
        g_wt1[c * HD + k] = __float2half(W1[t]);
        g_wt2[c * HD + k] = __float2half(W2[t]);
        g_wt3[c * HD + k] = __float2half(W3[t]);
    } else if (blockIdx.x < 96) {
        int t = (blockIdx.x - 64) * 256 + threadIdx.x;  // < 8192 = 64*128
        int r = t >> 7;
        g_wpt[t] = (r < 40) ? __float2half(Wp[t]) : __float2half(0.f);
    } else {
        int i = (blockIdx.x - 96) * 256 + threadIdx.x;  // one float4 (4 cols) per thread
        if (i < n * 32) {
            int d = g_degout[i >> 5]; if (d < 1) d = 1;
            float sv = rsqrtf((float)d);
            float4 a = ((const float4*)X)[i];
            __half2 h0 = __floats2half2_rn(a.x * sv, a.y * sv);
            __half2 h1 = __floats2half2_rn(a.z * sv, a.w * sv);
            ((__half2*)Xh)[i * 2]     = h0;
            ((__half2*)Xh)[i * 2 + 1] = h1;
        }
    }
}

// ---------------- exclusive scan of in-degrees -> row_ptr ----------------
__global__ void k_scan1(int n) {
    __shared__ int sh[512];
    int t = threadIdx.x;
    int i = blockIdx.x * 512 + t;
    int v = (i < n) ? g_degin[i] : 0;
    sh[t] = v;
    __syncthreads();
    #pragma unroll
    for (int off = 1; off < 512; off <<= 1) {
        int x = (t >= off) ? sh[t - off] : 0;
        __syncthreads();
        sh[t] += x;
        __syncthreads();
    }
    if (i < n) g_rowptr[i] = sh[t] - v;
    if (t == 511) g_bsum[blockIdx.x] = sh[511];
}

// scan2 folded in: each block serially prefixes the (<=196) block sums; also seeds cursor
__global__ void k_scan3(int nb, int n) {
    __shared__ int soff;
    if (threadIdx.x == 0) {
        int run = 0;
        for (int b = 0; b < blockIdx.x; b++) run += g_bsum[b];
        soff = run;
        if (blockIdx.x == nb - 1) g_rowptr[n] = run + g_bsum[nb - 1];
    }
    __syncthreads();
    int i = blockIdx.x * 512 + threadIdx.x;
    if (i < n) {
        int v = g_rowptr[i] + soff;
        g_rowptr[i] = v;
        g_cursor[i] = v;         // scatter cursor starts at row base
    }
}

// ---------------- CSR scatter (cursor holds absolute positions) ----------------
__global__ void k_scatter(const int* __restrict__ src, const int* __restrict__ dst, int e) {
    int i = blockIdx.x * blockDim.x + threadIdx.x;
    if (i < e) {
        int p = atomicAdd(&g_cursor[dst[i]], 1);
        g_col[p] = src[i];
    }
}

// ------------- HMMA GEMM: Y16[128-tile,128] = Xh @ W, split-K cp.async pipeline ----------
// 128x128 block tile, warp 32x64 (6 ldsm : 16 mma); K in two 64-chunks, double-buffered.
__global__ void __launch_bounds__(256) k_mm(const __half* __restrict__ Xh,
                                            const __half* __restrict__ Wt,
                                            __half* __restrict__ Y, int n) {
    extern __shared__ __half sh[];
    __half* Abuf[2] = { sh,                sh + 2 * 128 * CSTR };
    __half* Bbuf[2] = { sh + 128 * CSTR,   sh + 3 * 128 * CSTR };
    int tid = threadIdx.x;
    int base = blockIdx.x * 128;

    // ---- issue both chunk loads via cp.async ----
    #pragma unroll
    for (int ch = 0; ch < 2; ch++) {
        uint32_t asb = smem_u32(Abuf[ch]);
        uint32_t bsb = smem_u32(Bbuf[ch]);
        #pragma unroll
        for (int i = 0; i < 4; i++) {
            int slot = i * 256 + tid;          // 1024: row = slot/8, 8-half group j = slot%8
            int row = slot >> 3, j = slot & 7;
            int gr = base + row;
            const __half* gp = Xh + ((size_t)(gr < n ? gr : 0) * 128 + ch * 64 + j * 8);
            cp_async16(asb + (uint32_t)(row * CSTR + j * 8) * 2, gp, (gr < n) ? 16 : 0);
        }
        #pragma unroll
        for (int i = 0; i < 4; i++) {
            int slot = i * 256 + tid;
            int row = slot >> 3, j = slot & 7;
            const __half* gp = Wt + (row * 128 + ch * 64 + j * 8);
            cp_async16(bsb + (uint32_t)(row * CSTR + j * 8) * 2, gp, 16);
        }
        cp_commit();
    }

    int lane = tid & 31;
    int w = tid >> 5;
    int wm = (w & 3) * 32;     // row block
    int wn = (w >> 2) * 64;    // col block

    float acc[2][8][4];
    #pragma unroll
    for (int mi = 0; mi < 2; mi++)
        #pragma unroll
        for (int ni = 0; ni < 8; ni++)
            #pragma unroll
            for (int q = 0; q < 4; q++) acc[mi][ni][q] = 0.f;

    #pragma unroll
    for (int ch = 0; ch < 2; ch++) {
        if (ch == 0) asm volatile("cp.async.wait_group 1;" ::: "memory");
        else         asm volatile("cp.async.wait_group 0;" ::: "memory");
        __syncthreads();
        uint32_t a_base = smem_u32(Abuf[ch]);
        uint32_t b_base = smem_u32(Bbuf[ch]);
        #pragma unroll
        for (int k0 = 0; k0 < 64; k0 += 16) {
            uint32_t af[2][4];
            #pragma unroll
            for (int mi = 0; mi < 2; mi++) {
                int row = wm + mi * 16 + (lane & 15);
                int col = k0 + (lane >> 4) * 8;
                ldsm_x4(af[mi], a_base + (uint32_t)(row * CSTR + col) * 2);
            }
            uint32_t bf[4][4];
            #pragma unroll
            for (int p = 0; p < 4; p++) {
                int row = wn + p * 16 + ((lane >> 4) & 1) * 8 + (lane & 7);
                int col = k0 + ((lane >> 3) & 1) * 8;
                ldsm_x4(bf[p], b_base + (uint32_t)(row * CSTR + col) * 2);
            }
            #pragma unroll
            for (int mi = 0; mi < 2; mi++)
                #pragma unroll
                for (int p = 0; p < 4; p++) {
                    mma_f16(acc[mi][2 * p],     af[mi], bf[p][0], bf[p][1]);
                    mma_f16(acc[mi][2 * p + 1], af[mi], bf[p][2], bf[p][3]);
                }
        }
    }

    // ---- store fp16 messages ----
    __half2* Y2 = (__half2*)Y;
    #pragma unroll
    for (int mi = 0; mi < 2; mi++) {
        int r0 = base + wm + mi * 16 + (lane >> 2);
        int r1 = r0 + 8;
        #pragma unroll
        for (int ni = 0; ni < 8; ni++) {
            int col = wn + ni * 8 + (lane & 3) * 2;
            if (r0 < n) Y2[(r0 * 128 + col) >> 1] = __floats2half2_rn(acc[mi][ni][0], acc[mi][ni][1]);
            if (r1 < n) Y2[(r1 * 128 + col) >> 1] = __floats2half2_rn(acc[mi][ni][2], acc[mi][ni][3]);
        }
    }
}

// -------- aggregation core: half-warp per node, uint4 (16B) per lane --------
// acc[8]: 8 features per lane (lane ln covers halves [ln*8, ln*8+8))
__device__ __forceinline__ void acc8(float* acc, const uint4& v) {
    const __half2* hp = (const __half2*)&v;
    #pragma unroll
    for (int x = 0; x < 4; x++) {
        float2 f = __half22float2(hp[x]);
        acc[2 * x]     += f.x;
        acc[2 * x + 1] += f.y;
    }
}
__device__ __forceinline__ void agg_gather_w(const __half* __restrict__ T, int s, int e2,
                                             int ln, float* acc) {
    const uint4* T4 = (const uint4*)T;   // 8 halves per lane per row
    int i = s;
    for (; i + 4 <= e2; i += 4) {
        int c0 = g_col[i], c1 = g_col[i + 1], c2 = g_col[i + 2], c3 = g_col[i + 3];
        uint4 v0 = T4[c0 * 16 + ln];
        uint4 v1 = T4[c1 * 16 + ln];
        uint4 v2 = T4[c2 * 16 + ln];
        uint4 v3 = T4[c3 * 16 + ln];
        acc8(acc, v0); acc8(acc, v1); acc8(acc, v2); acc8(acc, v3);
    }
    for (; i < e2; i++) {
        uint4 v = T4[g_col[i] * 16 + ln];
        acc8(acc, v);
    }
}

// ---- agg -> fp16 hidden pre-scaled by out_norm (layers 1,2); norms inline ----
__global__ void __launch_bounds__(256) k_agg_h(const __half* __restrict__ T,
                                               const float* __restrict__ bias,
                                               __half* __restrict__ Ho, int n) {
    int lane = threadIdx.x & 31;
    int ln   = lane & 15;
    int node = ((blockIdx.x * 256 + threadIdx.x) >> 5) * 2 + (lane >> 4);
    if (node >= n) return;
    float acc[8];
    #pragma unroll
    for (int q = 0; q < 8; q++) acc[q] = 0.f;
    agg_gather_w(T, g_rowptr[node], g_rowptr[node + 1], ln, acc);

    int dI = g_degin[node];  if (dI < 1) dI = 1;
    int dO = g_degout[node]; if (dO < 1) dO = 1;
    float sc = rsqrtf((float)dI);
    float on = rsqrtf((float)dO);
    float4 b0 = ((const float4*)bias)[ln * 2];
    float4 b1 = ((const float4*)bias)[ln * 2 + 1];
    float r[8];
    r[0] = fmaxf(fmaf(acc[0], sc, b0.x), 0.f) * on;
    r[1] = fmaxf(fmaf(acc[1], sc, b0.y), 0.f) * on;
    r[2] = fmaxf(fmaf(acc[2], sc, b0.z), 0.f) * on;
    r[3] = fmaxf(fmaf(acc[3], sc, b0.w), 0.f) * on;
    r[4] = fmaxf(fmaf(acc[4], sc, b1.x), 0.f) * on;
    r[5] = fmaxf(fmaf(acc[5], sc, b1.y), 0.f) * on;
    r[6] = fmaxf(fmaf(acc[6], sc, b1.z), 0.f) * on;
    r[7] = fmaxf(fmaf(acc[7], sc, b1.w), 0.f) * on;
    uint4 o;
    ((__half2*)&o)[0] = __floats2half2_rn(r[0], r[1]);
    ((__half2*)&o)[1] = __floats2half2_rn(r[2], r[3]);
    ((__half2*)&o)[2] = __floats2half2_rn(r[4], r[5]);
    ((__half2*)&o)[3] = __floats2half2_rn(r[6], r[7]);
    ((uint4*)Ho)[node * 16 + ln] = o;
}

// ---- agg -> fp16 hidden, no out_norm (layer 3, feeds heads) ----
__global__ void __launch_bounds__(256) k_agg_o(const __half* __restrict__ T,
                                               const float* __restrict__ bias,
                                               __half* __restrict__ Ho, int n) {
    int lane = threadIdx.x & 31;
    int ln   = lane & 15;
    int node = ((blockIdx.x * 256 + threadIdx.x) >> 5) * 2 + (lane >> 4);
    if (node >= n) return;
    float acc[8];
    #pragma unroll
    for (int q = 0; q < 8; q++) acc[q] = 0.f;
    agg_gather_w(T, g_rowptr[node], g_rowptr[node + 1], ln, acc);

    int dI = g_degin[node]; if (dI < 1) dI = 1;
    float sc = rsqrtf((float)dI);
    float4 b0 = ((const float4*)bias)[ln * 2];
    float4 b1 = ((const float4*)bias)[ln * 2 + 1];
    float r[8];
    r[0] = fmaxf(fmaf(acc[0], sc, b0.x), 0.f);
    r[1] = fmaxf(fmaf(acc[1], sc, b0.y), 0.f);
    r[2] = fmaxf(fmaf(acc[2], sc, b0.z), 0.f);
    r[3] = fmaxf(fmaf(acc[3], sc, b0.w), 0.f);
    r[4] = fmaxf(fmaf(acc[4], sc, b1.x), 0.f);
    r[5] = fmaxf(fmaf(acc[5], sc, b1.y), 0.f);
    r[6] = fmaxf(fmaf(acc[6], sc, b1.z), 0.f);
    r[7] = fmaxf(fmaf(acc[7], sc, b1.w), 0.f);
    uint4 o;
    ((__half2*)&o)[0] = __floats2half2_rn(r[0], r[1]);
    ((__half2*)&o)[1] = __floats2half2_rn(r[2], r[3]);
    ((__half2*)&o)[2] = __floats2half2_rn(r[4], r[5]);
    ((__half2*)&o)[3] = __floats2half2_rn(r[6], r[7]);
    ((uint4*)Ho)[node * 16 + ln] = o;
}

// ---------------- seg_output ----------------
__global__ void k_seg(const float* __restrict__ Wp, const float* __restrict__ bp,
                      float* __restrict__ out, int n) {
    int c = threadIdx.x;
    if (c < 40) {
        float inv = 1.f / (float)n;
        float sum = bp[c];
        for (int k = 0; k < HD; k++) sum = fmaf(g_hg[k] * inv, Wp[c * HD + k], sum);
        out[c] = sum;
    }
}

// ---- CAM via HMMA: out[c*n + node] = dot(Wp[c,:], H[node,:]); fused column-sum of H ----
__global__ void __launch_bounds__(256) k_cam(const __half* __restrict__ Hh,
                                             float* __restrict__ out, int n) {
    extern __shared__ __half sh[];
    __half* As = sh;                    // 128 x SSTR (H tile)
    __half* Bs = sh + 128 * SSTR;       // 64 x SSTR (Wp fp16, padded)
    float*  Ts = (float*)sh;            // 128 x 65 fp32 (overlays As/Bs after mma)
    int tid = threadIdx.x;
    int base = blockIdx.x * 128;

    // ---- load H tile ----
    const uint4* H4 = (const uint4*)Hh;
    #pragma unroll
    for (int i = 0; i < 8; i++) {
        int slot = i * 256 + tid;
        int row = slot >> 4, j = slot & 15;
        int gr = base + row;
        uint4 v = make_uint4(0u, 0u, 0u, 0u);
        if (gr < n) v = H4[gr * 16 + j];
        *(uint4*)(As + row * SSTR + j * 8) = v;
    }
    // ---- load Wp fp16 (64 x 128, rows 40..63 zero) ----
    const uint4* P4 = (const uint4*)g_wpt;
    #pragma unroll
    for (int i = 0; i < 4; i++) {
        int slot = i * 256 + tid;           // 1024 slots
        int row = slot >> 4, j = slot & 15;
        uint4 v = P4[slot];
        *(uint4*)(Bs + row * SSTR + j * 8) = v;
    }
    __syncthreads();

    int lane = tid & 31;
    int w = tid >> 5;
    int wm = (w & 3) * 32;     // node rows
    int wn = (w >> 2) * 32;    // class cols

    float acc[2][4][4];
    #pragma unroll
    for (int mi = 0; mi < 2; mi++)
        #pragma unroll
        for (int ni = 0; ni < 4; ni++)
            #pragma unroll
            for (int q = 0; q < 4; q++) acc[mi][ni][q] = 0.f;

    uint32_t a_base = smem_u32(As);
    uint32_t b_base = smem_u32(Bs);

    #pragma unroll
    for (int k0 = 0; k0 < 128; k0 += 16) {
        uint32_t af[2][4];
        #pragma unroll
        for (int mi = 0; mi < 2; mi++) {
            int row = wm + mi * 16 + (lane & 15);
            int col = k0 + (lane >> 4) * 8;
            ldsm_x4(af[mi], a_base + (uint32_t)(row * SSTR + col) * 2);
        }
        uint32_t bf[2][4];
        #pragma unroll
        for (int p = 0; p < 2; p++) {
            int row = wn + p * 16 + ((lane >> 4) & 1) * 8 + (lane & 7);
            int col = k0 + ((lane >> 3) & 1) * 8;
            ldsm_x4(bf[p], b_base + (uint32_t)(row * SSTR + col) * 2);
        }
        #pragma unroll
        for (int mi = 0; mi < 2; mi++)
            #pragma unroll
            for (int p = 0; p < 2; p++) {
                mma_f16(acc[mi][2 * p],     af[mi], bf[p][0], bf[p][1]);
                mma_f16(acc[mi][2 * p + 1], af[mi], bf[p][2], bf[p][3]);
            }
    }

    // ---- fused column sum of this block's H tile (zeros beyond n are harmless) ----
    if (tid < 128) {
        float s = 0.f;
        #pragma unroll 8
        for (int r = 0; r < 128; r++) s += __half2float(As[r * SSTR + tid]);
        atomicAdd(&g_hg[tid], s);
    }
    __syncthreads();   // all reads of As/Bs done before Ts overwrite

    // ---- fragments -> padded fp32 smem tile ----
    #pragma unroll
    for (int mi = 0; mi < 2; mi++) {
        int r0 = wm + mi * 16 + (lane >> 2);
        int r1 = r0 + 8;
        #pragma unroll
        for (int ni = 0; ni < 4; ni++) {
            int col = wn + ni * 8 + (lane & 3) * 2;
            Ts[r0 * 65 + col]     = acc[mi][ni][0];
            Ts[r0 * 65 + col + 1] = acc[mi][ni][1];
            Ts[r1 * 65 + col]     = acc[mi][ni][2];
            Ts[r1 * 65 + col + 1] = acc[mi][ni][3];
        }
    }
    __syncthreads();

    // ---- coalesced transposed store: out[c*n + node] ----
    for (int idx = tid; idx < 40 * 128; idx += 256) {
        int c = idx >> 7, i = idx & 127;
        int node = base + i;
        if (node < n) out[c * n + node] = Ts[i * 65 + c];
    }
}

// ---------------- launch ----------------
extern "C" void kernel_launch(void* const* d_in, const int* in_sizes, int n_in,
                              void* d_out, int out_size) {
    const float* features = (const float*)d_in[0];
    const float* W1 = (const float*)d_in[1];
    const float* b1 = (const float*)d_in[2];
    const float* W2 = (const float*)d_in[3];
    const float* b2 = (const float*)d_in[4];
    const float* W3 = (const float*)d_in[5];
    const float* b3 = (const float*)d_in[6];
    const float* Wp = (const float*)d_in[7];
    const float* bp = (const float*)d_in[8];
    const int*  src = (const int*)d_in[9];
    const int*  dst = (const int*)d_in[10];
    float* out = (float*)d_out;

    int n = in_sizes[0] / HD;          // 100000
    int e = in_sizes[9];               // 1600000

    int ge  = (e + 255) / 256;
    int nb  = (n + 511) / 512;

    __half *h16a, *h16b, *m16, *wt1, *wt2, *wt3;
    void *degout, *degin, *hg;
    cudaGetSymbolAddress((void**)&h16a, g_h16a);
    cudaGetSymbolAddress((void**)&h16b, g_h16b);
    cudaGetSymbolAddress((void**)&m16,  g_m16);
    cudaGetSymbolAddress((void**)&wt1,  g_wt1);
    cudaGetSymbolAddress((void**)&wt2,  g_wt2);
    cudaGetSymbolAddress((void**)&wt3,  g_wt3);
    cudaGetSymbolAddress(&degout, g_degout);
    cudaGetSymbolAddress(&degin,  g_degin);
    cudaGetSymbolAddress(&hg,     g_hg);

    cudaFuncSetAttribute(k_mm,  cudaFuncAttributeMaxDynamicSharedMemorySize, MM_SMEM);
    cudaFuncSetAttribute(k_cam, cudaFuncAttributeMaxDynamicSharedMemorySize, CAM_SMEM);

    cudaMemsetAsync(degout, 0, n * sizeof(int));
    cudaMemsetAsync(degin,  0, n * sizeof(int));
    cudaMemsetAsync(hg,     0, HD * sizeof(float));

    int gt = (n + 127) / 128;   // GEMM tiles (128 rows)
    int gc = (n + 127) / 128;   // CAM tiles
    int ga = (n + 15) / 16;     // agg: 16 nodes per 256-thread block

    k_deg<<<(e / 2 + 255) / 256, 256>>>(src, dst, e);                               // 1
    k_prepall<<<96 + (n * 32 + 255) / 256, 256>>>(W1, W2, W3, Wp, features, h16a, n); // 2
    k_scan1<<<nb, 512>>>(n);                                                        // 3
    k_mm<<<gt, 256, MM_SMEM>>>(h16a, wt1, m16, n);                                  // 4 <- ncu profiles this
    k_scan3<<<nb, 512>>>(nb, n);                                                    // 5
    k_scatter<<<ge, 256>>>(src, dst, e);                                            // 6
    k_agg_h<<<ga, 256>>>(m16, b1, h16b, n);                                         // 7
    k_mm<<<gt, 256, MM_SMEM>>>(h16b, wt2, m16, n);                                  // 8
    k_agg_h<<<ga, 256>>>(m16, b2, h16a, n);                                         // 9
    k_mm<<<gt, 256, MM_SMEM>>>(h16a, wt3, m16, n);                                  // 10
    k_agg_o<<<ga, 256>>>(m16, b3, h16b, n);                                         // 11

    // heads (fp16 H in h16b): cam fuses colsum; seg reads g_hg after cam
    k_cam<<<gc, 256, CAM_SMEM>>>(h16b, out + 40, n);                                // 12
    k_seg<<<1, 64>>>(Wp, bp, out, n);                                               // 13
}

// round 15
// speedup vs baseline: 1.0985x; 1.0327x over previous
#include <cuda_runtime.h>
#include <cuda_fp16.h>
#include <cuda_bf16.h>
#include <cstdint>

#define NMAX 100000
#define EMAX 1600000
#define HD   128

// ---------------- scratch (device globals; no allocation allowed) ----------------
__device__ __half g_h16a[NMAX * HD];    // fp16 hidden (pre-scaled by out_norm)
__device__ __half g_h16b[NMAX * HD];
__device__ __half g_m16[NMAX * HD];     // fp16 messages (GEMM output)
__device__ float g_hg[HD];
__device__ int   g_degout[NMAX];
__device__ int   g_degin[NMAX];
__device__ int   g_cursor[NMAX];
__device__ int   g_rowptr[NMAX + 1];
__device__ int   g_col[EMAX];
__device__ int   g_bsum[512];
__device__ __half g_wt1[HD * HD];       // W^T fp16: [n][k]
__device__ __half g_wt2[HD * HD];
__device__ __half g_wt3[HD * HD];
__device__ __half g_wpt[64 * HD];       // Wp fp16 [64][128], rows 40..63 zero

// ================= warp MMA helpers (baseline PTX, compiles on compute_103) ====
__device__ __forceinline__ uint32_t smem_u32(const void* p) {
    uint32_t a;
    asm("{ .reg .u64 t; cvta.to.shared.u64 t, %1; cvt.u32.u64 %0, t; }" : "=r"(a) : "l"(p));
    return a;
}
__device__ __forceinline__ void ldsm_x4(uint32_t* r, uint32_t addr) {
    asm volatile("ldmatrix.sync.aligned.m8n8.x4.shared.b16 {%0,%1,%2,%3}, [%4];"
                 : "=r"(r[0]), "=r"(r[1]), "=r"(r[2]), "=r"(r[3]) : "r"(addr));
}
__device__ __forceinline__ void mma_f16(float* d, const uint32_t* a, uint32_t b0, uint32_t b1) {
    asm volatile("mma.sync.aligned.m16n8k16.row.col.f32.f16.f16.f32 "
                 "{%0,%1,%2,%3}, {%4,%5,%6,%7}, {%8,%9}, {%0,%1,%2,%3};"
                 : "+f"(d[0]), "+f"(d[1]), "+f"(d[2]), "+f"(d[3])
                 : "r"(a[0]), "r"(a[1]), "r"(a[2]), "r"(a[3]), "r"(b0), "r"(b1));
}
__device__ __forceinline__ void cp_async16(uint32_t daddr, const void* gptr, int nbytes) {
    asm volatile("cp.async.cg.shared.global [%0], [%1], 16, %2;"
                 :: "r"(daddr), "l"(gptr), "r"(nbytes) : "memory");
}
__device__ __forceinline__ void cp_commit() { asm volatile("cp.async.commit_group;" ::: "memory"); }

#define SSTR 136   // smem row stride in halves for cam (272B)
#define CSTR 72    // k_mm chunk row stride in halves (144B: 16B-aligned, 16B bank shift)
#define MM_SMEM (4 * 128 * CSTR * 2)    // A0,B0,A1,B1 = 73728 B
#define CAM_SMEM (192 * SSTR * 2)       // 128-row H tile + 64-row Wp tile (fp32 Ts overlays)

// ---------------- degrees (2 edges per thread) ----------------
__global__ void k_deg(const int* __restrict__ src, const int* __restrict__ dst, int e) {
    int i = blockIdx.x * blockDim.x + threadIdx.x;
    int eh = e >> 1;
    if (i < eh) {
        int2 s = ((const int2*)src)[i];
        int2 d = ((const int2*)dst)[i];
        atomicAdd(&g_degout[s.x], 1);
        atomicAdd(&g_degout[s.y], 1);
        atomicAdd(&g_degin[d.x], 1);
        atomicAdd(&g_degin[d.y], 1);
    }
    if (i == 0 && (e & 1)) {
        atomicAdd(&g_degout[src[e - 1]], 1);
        atomicAdd(&g_degin[dst[e - 1]], 1);
    }
}

// ------- fused prep: [0,64) W^T fp16; [64,96) Wp fp16 padded; [96,..) X*out_norm fp16 -----
__global__ void k_prepall(const float* __restrict__ W1, const float* __restrict__ W2,
                          const float* __restrict__ W3, const float* __restrict__ Wp,
                          const float* __restrict__ X, __half* __restrict__ Xh, int n) {
    if (blockIdx.x < 64) {
        int t = blockIdx.x * 256 + threadIdx.x;     // < 16384
        int k = t >> 7, c = t & 127;                // t = k*128 + c
        g_wt1[c * HD + k] = __float2half(W1[t]);
        g_wt2[c * HD + k] = __float2half(W2[t]);
        g_wt3[c * HD + k] = __float2half(W3[t]);
    } else if (blockIdx.x < 96) {
        int t = (blockIdx.x - 64) * 256 + threadIdx.x;  // < 8192 = 64*128
        int r = t >> 7;
        g_wpt[t] = (r < 40) ? __float2half(Wp[t]) : __float2half(0.f);
    } else {
        int i = (blockIdx.x - 96) * 256 + threadIdx.x;  // one float4 (4 cols) per thread
        if (i < n * 32) {
            int d = g_degout[i >> 5]; if (d < 1) d = 1;
            float sv = rsqrtf((float)d);
            float4 a = ((const float4*)X)[i];
            __half2 h0 = __floats2half2_rn(a.x * sv, a.y * sv);
            __half2 h1 = __floats2half2_rn(a.z * sv, a.w * sv);
            ((__half2*)Xh)[i * 2]     = h0;
            ((__half2*)Xh)[i * 2 + 1] = h1;
        }
    }
}

// ---------------- exclusive scan of in-degrees -> row_ptr ----------------
__global__ void k_scan1(int n) {
    __shared__ int sh[512];
    int t = threadIdx.x;
    int i = blockIdx.x * 512 + t;
    int v = (i < n) ? g_degin[i] : 0;
    sh[t] = v;
    __syncthreads();
    #pragma unroll
    for (int off = 1; off < 512; off <<= 1) {
        int x = (t >= off) ? sh[t - off] : 0;
        __syncthreads();
        sh[t] += x;
        __syncthreads();
    }
    if (i < n) g_rowptr[i] = sh[t] - v;
    if (t == 511) g_bsum[blockIdx.x] = sh[511];
}

// scan2 folded in: each block serially prefixes the (<=196) block sums; also seeds cursor
__global__ void k_scan3(int nb, int n) {
    __shared__ int soff;
    if (threadIdx.x == 0) {
        int run = 0;
        for (int b = 0; b < blockIdx.x; b++) run += g_bsum[b];
        soff = run;
        if (blockIdx.x == nb - 1) g_rowptr[n] = run + g_bsum[nb - 1];
    }
    __syncthreads();
    int i = blockIdx.x * 512 + threadIdx.x;
    if (i < n) {
        int v = g_rowptr[i] + soff;
        g_rowptr[i] = v;
        g_cursor[i] = v;         // scatter cursor starts at row base
    }
}

// ---------------- CSR scatter (cursor holds absolute positions) ----------------
__global__ void k_scatter(const int* __restrict__ src, const int* __restrict__ dst, int e) {
    int i = blockIdx.x * blockDim.x + threadIdx.x;
    if (i < e) {
        int p = atomicAdd(&g_cursor[dst[i]], 1);
        g_col[p] = src[i];
    }
}

// ------------- HMMA GEMM: Y16[128-tile,128] = Xh @ W, split-K cp.async pipeline ----------
// 128x128 block tile, warp 32x64 (6 ldsm : 16 mma); K in two 64-chunks, double-buffered.
__global__ void __launch_bounds__(256) k_mm(const __half* __restrict__ Xh,
                                            const __half* __restrict__ Wt,
                                            __half* __restrict__ Y, int n) {
    extern __shared__ __half sh[];
    __half* Abuf[2] = { sh,                sh + 2 * 128 * CSTR };
    __half* Bbuf[2] = { sh + 128 * CSTR,   sh + 3 * 128 * CSTR };
    int tid = threadIdx.x;
    int base = blockIdx.x * 128;

    // ---- issue both chunk loads via cp.async ----
    #pragma unroll
    for (int ch = 0; ch < 2; ch++) {
        uint32_t asb = smem_u32(Abuf[ch]);
        uint32_t bsb = smem_u32(Bbuf[ch]);
        #pragma unroll
        for (int i = 0; i < 4; i++) {
            int slot = i * 256 + tid;          // 1024: row = slot/8, 8-half group j = slot%8
            int row = slot >> 3, j = slot & 7;
            int gr = base + row;
            const __half* gp = Xh + ((size_t)(gr < n ? gr : 0) * 128 + ch * 64 + j * 8);
            cp_async16(asb + (uint32_t)(row * CSTR + j * 8) * 2, gp, (gr < n) ? 16 : 0);
        }
        #pragma unroll
        for (int i = 0; i < 4; i++) {
            int slot = i * 256 + tid;
            int row = slot >> 3, j = slot & 7;
            const __half* gp = Wt + (row * 128 + ch * 64 + j * 8);
            cp_async16(bsb + (uint32_t)(row * CSTR + j * 8) * 2, gp, 16);
        }
        cp_commit();
    }

    int lane = tid & 31;
    int w = tid >> 5;
    int wm = (w & 3) * 32;     // row block
    int wn = (w >> 2) * 64;    // col block

    float acc[2][8][4];
    #pragma unroll
    for (int mi = 0; mi < 2; mi++)
        #pragma unroll
        for (int ni = 0; ni < 8; ni++)
            #pragma unroll
            for (int q = 0; q < 4; q++) acc[mi][ni][q] = 0.f;

    #pragma unroll
    for (int ch = 0; ch < 2; ch++) {
        if (ch == 0) asm volatile("cp.async.wait_group 1;" ::: "memory");
        else         asm volatile("cp.async.wait_group 0;" ::: "memory");
        __syncthreads();
        uint32_t a_base = smem_u32(Abuf[ch]);
        uint32_t b_base = smem_u32(Bbuf[ch]);
        #pragma unroll
        for (int k0 = 0; k0 < 64; k0 += 16) {
            uint32_t af[2][4];
            #pragma unroll
            for (int mi = 0; mi < 2; mi++) {
                int row = wm + mi * 16 + (lane & 15);
                int col = k0 + (lane >> 4) * 8;
                ldsm_x4(af[mi], a_base + (uint32_t)(row * CSTR + col) * 2);
            }
            uint32_t bf[4][4];
            #pragma unroll
            for (int p = 0; p < 4; p++) {
                int row = wn + p * 16 + ((lane >> 4) & 1) * 8 + (lane & 7);
                int col = k0 + ((lane >> 3) & 1) * 8;
                ldsm_x4(bf[p], b_base + (uint32_t)(row * CSTR + col) * 2);
            }
            #pragma unroll
            for (int mi = 0; mi < 2; mi++)
                #pragma unroll
                for (int p = 0; p < 4; p++) {
                    mma_f16(acc[mi][2 * p],     af[mi], bf[p][0], bf[p][1]);
                    mma_f16(acc[mi][2 * p + 1], af[mi], bf[p][2], bf[p][3]);
                }
        }
    }

    // ---- store fp16 messages ----
    __half2* Y2 = (__half2*)Y;
    #pragma unroll
    for (int mi = 0; mi < 2; mi++) {
        int r0 = base + wm + mi * 16 + (lane >> 2);
        int r1 = r0 + 8;
        #pragma unroll
        for (int ni = 0; ni < 8; ni++) {
            int col = wn + ni * 8 + (lane & 3) * 2;
            if (r0 < n) Y2[(r0 * 128 + col) >> 1] = __floats2half2_rn(acc[mi][ni][0], acc[mi][ni][1]);
            if (r1 < n) Y2[(r1 * 128 + col) >> 1] = __floats2half2_rn(acc[mi][ni][2], acc[mi][ni][3]);
        }
    }
}

// -------- aggregation core: half-warp per node, uint4 (16B) per lane --------
__device__ __forceinline__ void acc8(float* acc, const uint4& v) {
    const __half2* hp = (const __half2*)&v;
    #pragma unroll
    for (int x = 0; x < 4; x++) {
        float2 f = __half22float2(hp[x]);
        acc[2 * x]     += f.x;
        acc[2 * x + 1] += f.y;
    }
}
__device__ __forceinline__ void agg_gather_w(const __half* __restrict__ T, int s, int e2,
                                             int ln, float* acc) {
    const uint4* T4 = (const uint4*)T;   // 8 halves per lane per row
    int i = s;
    for (; i + 4 <= e2; i += 4) {
        int c0 = g_col[i], c1 = g_col[i + 1], c2 = g_col[i + 2], c3 = g_col[i + 3];
        uint4 v0 = T4[c0 * 16 + ln];
        uint4 v1 = T4[c1 * 16 + ln];
        uint4 v2 = T4[c2 * 16 + ln];
        uint4 v3 = T4[c3 * 16 + ln];
        acc8(acc, v0); acc8(acc, v1); acc8(acc, v2); acc8(acc, v3);
    }
    for (; i < e2; i++) {
        uint4 v = T4[g_col[i] * 16 + ln];
        acc8(acc, v);
    }
}

// ---- agg -> fp16 hidden pre-scaled by out_norm (layers 1,2); norms inline ----
__global__ void __launch_bounds__(256) k_agg_h(const __half* __restrict__ T,
                                               const float* __restrict__ bias,
                                               __half* __restrict__ Ho, int n) {
    int lane = threadIdx.x & 31;
    int ln   = lane & 15;
    int node = ((blockIdx.x * 256 + threadIdx.x) >> 5) * 2 + (lane >> 4);
    if (node >= n) return;
    float acc[8];
    #pragma unroll
    for (int q = 0; q < 8; q++) acc[q] = 0.f;
    agg_gather_w(T, g_rowptr[node], g_rowptr[node + 1], ln, acc);

    int dI = g_degin[node];  if (dI < 1) dI = 1;
    int dO = g_degout[node]; if (dO < 1) dO = 1;
    float sc = rsqrtf((float)dI);
    float on = rsqrtf((float)dO);
    float4 b0 = ((const float4*)bias)[ln * 2];
    float4 b1 = ((const float4*)bias)[ln * 2 + 1];
    float r[8];
    r[0] = fmaxf(fmaf(acc[0], sc, b0.x), 0.f) * on;
    r[1] = fmaxf(fmaf(acc[1], sc, b0.y), 0.f) * on;
    r[2] = fmaxf(fmaf(acc[2], sc, b0.z), 0.f) * on;
    r[3] = fmaxf(fmaf(acc[3], sc, b0.w), 0.f) * on;
    r[4] = fmaxf(fmaf(acc[4], sc, b1.x), 0.f) * on;
    r[5] = fmaxf(fmaf(acc[5], sc, b1.y), 0.f) * on;
    r[6] = fmaxf(fmaf(acc[6], sc, b1.z), 0.f) * on;
    r[7] = fmaxf(fmaf(acc[7], sc, b1.w), 0.f) * on;
    uint4 o;
    ((__half2*)&o)[0] = __floats2half2_rn(r[0], r[1]);
    ((__half2*)&o)[1] = __floats2half2_rn(r[2], r[3]);
    ((__half2*)&o)[2] = __floats2half2_rn(r[4], r[5]);
    ((__half2*)&o)[3] = __floats2half2_rn(r[6], r[7]);
    ((uint4*)Ho)[node * 16 + ln] = o;
}

// ---- agg -> fp16 hidden, no out_norm (layer 3, feeds heads) ----
__global__ void __launch_bounds__(256) k_agg_o(const __half* __restrict__ T,
                                               const float* __restrict__ bias,
                                               __half* __restrict__ Ho, int n) {
    int lane = threadIdx.x & 31;
    int ln   = lane & 15;
    int node = ((blockIdx.x * 256 + threadIdx.x) >> 5) * 2 + (lane >> 4);
    if (node >= n) return;
    float acc[8];
    #pragma unroll
    for (int q = 0; q < 8; q++) acc[q] = 0.f;
    agg_gather_w(T, g_rowptr[node], g_rowptr[node + 1], ln, acc);

    int dI = g_degin[node]; if (dI < 1) dI = 1;
    float sc = rsqrtf((float)dI);
    float4 b0 = ((const float4*)bias)[ln * 2];
    float4 b1 = ((const float4*)bias)[ln * 2 + 1];
    float r[8];
    r[0] = fmaxf(fmaf(acc[0], sc, b0.x), 0.f);
    r[1] = fmaxf(fmaf(acc[1], sc, b0.y), 0.f);
    r[2] = fmaxf(fmaf(acc[2], sc, b0.z), 0.f);
    r[3] = fmaxf(fmaf(acc[3], sc, b0.w), 0.f);
    r[4] = fmaxf(fmaf(acc[4], sc, b1.x), 0.f);
    r[5] = fmaxf(fmaf(acc[5], sc, b1.y), 0.f);
    r[6] = fmaxf(fmaf(acc[6], sc, b1.z), 0.f);
    r[7] = fmaxf(fmaf(acc[7], sc, b1.w), 0.f);
    uint4 o;
    ((__half2*)&o)[0] = __floats2half2_rn(r[0], r[1]);
    ((__half2*)&o)[1] = __floats2half2_rn(r[2], r[3]);
    ((__half2*)&o)[2] = __floats2half2_rn(r[4], r[5]);
    ((__half2*)&o)[3] = __floats2half2_rn(r[6], r[7]);
    ((uint4*)Ho)[node * 16 + ln] = o;
}

// ---------------- seg_output ----------------
__global__ void k_seg(const float* __restrict__ Wp, const float* __restrict__ bp,
                      float* __restrict__ out, int n) {
    int c = threadIdx.x;
    if (c < 40) {
        float inv = 1.f / (float)n;
        float sum = bp[c];
        for (int k = 0; k < HD; k++) sum = fmaf(g_hg[k] * inv, Wp[c * HD + k], sum);
        out[c] = sum;
    }
}

// ---- CAM via HMMA: out[c*n + node] = dot(Wp[c,:], H[node,:]); fused column-sum of H ----
__global__ void __launch_bounds__(256) k_cam(const __half* __restrict__ Hh,
                                             float* __restrict__ out, int n) {
    extern __shared__ __half sh[];
    __half* As = sh;                    // 128 x SSTR (H tile)
    __half* Bs = sh + 128 * SSTR;       // 64 x SSTR (Wp fp16, padded)
    float*  Ts = (float*)sh;            // 128 x 65 fp32 (overlays As/Bs after mma)
    int tid = threadIdx.x;
    int base = blockIdx.x * 128;

    // ---- load H tile ----
    const uint4* H4 = (const uint4*)Hh;
    #pragma unroll
    for (int i = 0; i < 8; i++) {
        int slot = i * 256 + tid;
        int row = slot >> 4, j = slot & 15;
        int gr = base + row;
        uint4 v = make_uint4(0u, 0u, 0u, 0u);
        if (gr < n) v = H4[gr * 16 + j];
        *(uint4*)(As + row * SSTR + j * 8) = v;
    }
    // ---- load Wp fp16 (64 x 128, rows 40..63 zero) ----
    const uint4* P4 = (const uint4*)g_wpt;
    #pragma unroll
    for (int i = 0; i < 4; i++) {
        int slot = i * 256 + tid;           // 1024 slots
        int row = slot >> 4, j = slot & 15;
        uint4 v = P4[slot];
        *(uint4*)(Bs + row * SSTR + j * 8) = v;
    }
    __syncthreads();

    int lane = tid & 31;
    int w = tid >> 5;
    int wm = (w & 3) * 32;     // node rows
    int wn = (w >> 2) * 32;    // class cols

    float acc[2][4][4];
    #pragma unroll
    for (int mi = 0; mi < 2; mi++)
        #pragma unroll
        for (int ni = 0; ni < 4; ni++)
            #pragma unroll
            for (int q = 0; q < 4; q++) acc[mi][ni][q] = 0.f;

    uint32_t a_base = smem_u32(As);
    uint32_t b_base = smem_u32(Bs);

    #pragma unroll
    for (int k0 = 0; k0 < 128; k0 += 16) {
        uint32_t af[2][4];
        #pragma unroll
        for (int mi = 0; mi < 2; mi++) {
            int row = wm + mi * 16 + (lane & 15);
            int col = k0 + (lane >> 4) * 8;
            ldsm_x4(af[mi], a_base + (uint32_t)(row * SSTR + col) * 2);
        }
        uint32_t bf[2][4];
        #pragma unroll
        for (int p = 0; p < 2; p++) {
            int row = wn + p * 16 + ((lane >> 4) & 1) * 8 + (lane & 7);
            int col = k0 + ((lane >> 3) & 1) * 8;
            ldsm_x4(bf[p], b_base + (uint32_t)(row * SSTR + col) * 2);
        }
        #pragma unroll
        for (int mi = 0; mi < 2; mi++)
            #pragma unroll
            for (int p = 0; p < 2; p++) {
                mma_f16(acc[mi][2 * p],     af[mi], bf[p][0], bf[p][1]);
                mma_f16(acc[mi][2 * p + 1], af[mi], bf[p][2], bf[p][3]);
            }
    }

    // ---- fused column sum of this block's H tile (zeros beyond n are harmless) ----
    if (tid < 128) {
        float s = 0.f;
        #pragma unroll 8
        for (int r = 0; r < 128; r++) s += __half2float(As[r * SSTR + tid]);
        atomicAdd(&g_hg[tid], s);
    }
    __syncthreads();   // all reads of As/Bs done before Ts overwrite

    // ---- fragments -> padded fp32 smem tile ----
    #pragma unroll
    for (int mi = 0; mi < 2; mi++) {
        int r0 = wm + mi * 16 + (lane >> 2);
        int r1 = r0 + 8;
        #pragma unroll
        for (int ni = 0; ni < 4; ni++) {
            int col = wn + ni * 8 + (lane & 3) * 2;
            Ts[r0 * 65 + col]     = acc[mi][ni][0];
            Ts[r0 * 65 + col + 1] = acc[mi][ni][1];
            Ts[r1 * 65 + col]     = acc[mi][ni][2];
            Ts[r1 * 65 + col + 1] = acc[mi][ni][3];
        }
    }
    __syncthreads();

    // ---- coalesced transposed store: out[c*n + node] ----
    for (int idx = tid; idx < 40 * 128; idx += 256) {
        int c = idx >> 7, i = idx & 127;
        int node = base + i;
        if (node < n) out[c * n + node] = Ts[i * 65 + c];
    }
}

// ---------------- launch ----------------
extern "C" void kernel_launch(void* const* d_in, const int* in_sizes, int n_in,
                              void* d_out, int out_size) {
    const float* features = (const float*)d_in[0];
    const float* W1 = (const float*)d_in[1];
    const float* b1 = (const float*)d_in[2];
    const float* W2 = (const float*)d_in[3];
    const float* b2 = (const float*)d_in[4];
    const float* W3 = (const float*)d_in[5];
    const float* b3 = (const float*)d_in[6];
    const float* Wp = (const float*)d_in[7];
    const float* bp = (const float*)d_in[8];
    const int*  src = (const int*)d_in[9];
    const int*  dst = (const int*)d_in[10];
    float* out = (float*)d_out;

    int n = in_sizes[0] / HD;          // 100000
    int e = in_sizes[9];               // 1600000

    int ge  = (e + 255) / 256;
    int nb  = (n + 511) / 512;

    __half *h16a, *h16b, *m16, *wt1, *wt2, *wt3;
    void *degout, *degin, *hg;
    cudaGetSymbolAddress((void**)&h16a, g_h16a);
    cudaGetSymbolAddress((void**)&h16b, g_h16b);
    cudaGetSymbolAddress((void**)&m16,  g_m16);
    cudaGetSymbolAddress((void**)&wt1,  g_wt1);
    cudaGetSymbolAddress((void**)&wt2,  g_wt2);
    cudaGetSymbolAddress((void**)&wt3,  g_wt3);
    cudaGetSymbolAddress(&degout, g_degout);
    cudaGetSymbolAddress(&degin,  g_degin);
    cudaGetSymbolAddress(&hg,     g_hg);

    cudaFuncSetAttribute(k_mm,  cudaFuncAttributeMaxDynamicSharedMemorySize, MM_SMEM);
    cudaFuncSetAttribute(k_cam, cudaFuncAttributeMaxDynamicSharedMemorySize, CAM_SMEM);

    // side stream + fork/join events, created once on the (uncaptured) correctness call
    static cudaStream_t s2 = nullptr;
    static cudaEvent_t evA = nullptr, evB = nullptr;
    if (s2 == nullptr) {
        cudaStreamCreateWithFlags(&s2, cudaStreamNonBlocking);
        cudaEventCreateWithFlags(&evA, cudaEventDisableTiming);
        cudaEventCreateWithFlags(&evB, cudaEventDisableTiming);
    }

    cudaMemsetAsync(degout, 0, n * sizeof(int));
    cudaMemsetAsync(degin,  0, n * sizeof(int));
    cudaMemsetAsync(hg,     0, HD * sizeof(float));

    int gt = (n + 127) / 128;   // GEMM tiles (128 rows)
    int gc = (n + 127) / 128;   // CAM tiles
    int ga = (n + 15) / 16;     // agg: 16 nodes per 256-thread block

    // main stream: deg -> prepall -> mm1 ; side stream s2: scan1 -> scan3 -> scatter
    k_deg<<<(e / 2 + 255) / 256, 256>>>(src, dst, e);                               // 1
    cudaEventRecord(evA, 0);
    k_prepall<<<96 + (n * 32 + 255) / 256, 256>>>(W1, W2, W3, Wp, features, h16a, n); // 2
    cudaStreamWaitEvent(s2, evA, 0);
    k_scan1<<<nb, 512, 0, s2>>>(n);                                                 // 3 (s2)
    k_mm<<<gt, 256, MM_SMEM>>>(h16a, wt1, m16, n);                                  // 4 <- ncu profiles this
    k_scan3<<<nb, 512, 0, s2>>>(nb, n);                                             // 5 (s2)
    k_scatter<<<ge, 256, 0, s2>>>(src, dst, e);                                     // 6 (s2)
    cudaEventRecord(evB, s2);
    cudaStreamWaitEvent(0, evB, 0);                                                 // join

    k_agg_h<<<ga, 256>>>(m16, b1, h16b, n);                                         // 7
    k_mm<<<gt, 256, MM_SMEM>>>(h16b, wt2, m16, n);                                  // 8
    k_agg_h<<<ga, 256>>>(m16, b2, h16a, n);                                         // 9
    k_mm<<<gt, 256, MM_SMEM>>>(h16a, wt3, m16, n);                                  // 10
    k_agg_o<<<ga, 256>>>(m16, b3, h16b, n);                                         // 11

    // heads (fp16 H in h16b): cam fuses colsum; seg reads g_hg after cam
    k_cam<<<gc, 256, CAM_SMEM>>>(h16b, out + 40, n);                                // 12
    k_seg<<<1, 64>>>(Wp, bp, out, n);                                               // 13
}